// round 15
// baseline (speedup 1.0000x reference)
#include <cuda_runtime.h>
#include <cuda_fp16.h>
#include <cstdint>

// ---------------------------------------------------------------------------
// Problem constants
// ---------------------------------------------------------------------------
#define BZ   2
#define SQ   2048
#define DM   1024
#define NH   16
#define DH   64
#define FFD  4096
#define MROWS (BZ * SQ)            // 4096

// ---------------------------------------------------------------------------
// Scratch (device globals).
// ---------------------------------------------------------------------------
__device__ __half g_srch [(size_t)MROWS * DM];
__device__ __half g_wqkvh[(size_t)3 * DM * DM];
__device__ float  g_bqkv [(size_t)3 * DM];
__device__ __half g_owh  [(size_t)DM * DM];
__device__ __half g_w1h  [(size_t)FFD * DM];
__device__ __half g_w2h  [(size_t)DM * FFD];
__device__ __half g_qkvh [(size_t)MROWS * 3 * DM];
__device__ __half g_ctxh [(size_t)MROWS * DM];
__device__ __half g_x1h  [(size_t)MROWS * DM];
__device__ __half g_ffh  [(size_t)MROWS * FFD];
__device__ float  g_t1   [(size_t)MROWS * DM];
__device__ float  g_t2   [(size_t)MROWS * DM];
__device__ float  g_t0   [(size_t)MROWS * DM];

// ---------------------------------------------------------------------------
// Helpers
// ---------------------------------------------------------------------------
__device__ __forceinline__ uint32_t smem_u32(const void* p) {
    return (uint32_t)__cvta_generic_to_shared(p);
}

#define LDMX4(r0, r1, r2, r3, addr)                                         \
    asm volatile("ldmatrix.sync.aligned.m8n8.x4.shared.b16 {%0,%1,%2,%3}, [%4];" \
                 : "=r"(r0), "=r"(r1), "=r"(r2), "=r"(r3) : "r"(addr))

#define LDMX4T(r0, r1, r2, r3, addr)                                        \
    asm volatile("ldmatrix.sync.aligned.m8n8.x4.trans.shared.b16 {%0,%1,%2,%3}, [%4];" \
                 : "=r"(r0), "=r"(r1), "=r"(r2), "=r"(r3) : "r"(addr))

#define MMA16816(d, a, b0, b1)                                              \
    asm volatile("mma.sync.aligned.m16n8k16.row.col.f32.f16.f16.f32 "        \
                 "{%0,%1,%2,%3}, {%4,%5,%6,%7}, {%8,%9}, {%0,%1,%2,%3};"     \
                 : "+f"(d[0]), "+f"(d[1]), "+f"(d[2]), "+f"(d[3])            \
                 : "r"(a[0]), "r"(a[1]), "r"(a[2]), "r"(a[3]),               \
                   "r"(b0), "r"(b1))

#define CP_ASYNC16(dst, src)                                                \
    asm volatile("cp.async.cg.shared.global [%0], [%1], 16;"                 \
                 :: "r"(dst), "l"(src))
#define CP_COMMIT  asm volatile("cp.async.commit_group;")
#define CP_WAIT0   asm volatile("cp.async.wait_group 0;")
#define CP_WAIT1   asm volatile("cp.async.wait_group 1;")

// swizzled byte offset within a 64-half-wide (128B) row tile
__device__ __forceinline__ uint32_t swz(int r, int c16) {
    return (uint32_t)(r * 128 + ((c16 ^ (r & 7)) * 16));
}

__device__ __forceinline__ void store2(float* C, long idx, float v0, float v1) {
    *(float2*)&C[idx] = make_float2(v0, v1);
}
__device__ __forceinline__ void store2(__half* C, long idx, float v0, float v1) {
    *(__half2*)&C[idx] = __floats2half2_rn(v0, v1);
}

__device__ __forceinline__ float block_reduce_sum(float v) {
    __shared__ float sh[32];
    const unsigned mask = 0xffffffffu;
    #pragma unroll
    for (int o = 16; o > 0; o >>= 1) v += __shfl_xor_sync(mask, v, o);
    int lane = threadIdx.x & 31, w = threadIdx.x >> 5;
    __syncthreads();
    if (lane == 0) sh[w] = v;
    __syncthreads();
    int nw = (blockDim.x + 31) >> 5;
    if (w == 0) {
        v = (lane < nw) ? sh[lane] : 0.0f;
        #pragma unroll
        for (int o = 16; o > 0; o >>= 1) v += __shfl_xor_sync(mask, v, o);
        if (lane == 0) sh[0] = v;
    }
    __syncthreads();
    return sh[0];
}

// ---------------------------------------------------------------------------
// One-shot segmented f32 -> f16 conversion (src + weights); bias pack.
// ---------------------------------------------------------------------------
__global__ void __launch_bounds__(256)
convert_all(const float* __restrict__ src, const float* __restrict__ qw,
            const float* __restrict__ kw,  const float* __restrict__ vw,
            const float* __restrict__ ow,  const float* __restrict__ w1,
            const float* __restrict__ w2,
            __half* __restrict__ srch, __half* __restrict__ wqkv,
            __half* __restrict__ owh,  __half* __restrict__ w1h,
            __half* __restrict__ w2h)
{
    long i = ((long)blockIdx.x * 256 + threadIdx.x) * 4;
    const float* in; __half* out; long off;
    if      (i <  4194304L) { in = src; out = srch;           off = i; }
    else if (i <  5242880L) { in = qw;  out = wqkv;           off = i - 4194304L; }
    else if (i <  6291456L) { in = kw;  out = wqkv + 1048576; off = i - 5242880L; }
    else if (i <  7340032L) { in = vw;  out = wqkv + 2097152; off = i - 6291456L; }
    else if (i <  8388608L) { in = ow;  out = owh;            off = i - 7340032L; }
    else if (i < 12582912L) { in = w1;  out = w1h;            off = i - 8388608L; }
    else                    { in = w2;  out = w2h;            off = i - 12582912L; }
    float4 t = *(const float4*)&in[off];
    __half2* d = (__half2*)&out[off];
    d[0] = __floats2half2_rn(t.x, t.y);
    d[1] = __floats2half2_rn(t.z, t.w);
}

__global__ void __launch_bounds__(256)
pack_bias(const float* __restrict__ qb, const float* __restrict__ kb,
          const float* __restrict__ vb, float* __restrict__ out)
{
    int i = blockIdx.x * 256 + threadIdx.x;
    float v = (i < 1024) ? qb[i] : (i < 2048 ? kb[i - 1024] : vb[i - 2048]);
    out[i] = v;
}

// ---------------------------------------------------------------------------
// Pipelined fp16 GEMM (TN) v2: block tile 128M x 256N x 64K, warp tile 64x64
// (8 warps as 2m x 4n). 3-stage cp.async (48 KB/stage => 144 KB smem),
// ONE syncthreads per iter. Per 16-K step: 8 LDMX4 feed 32 MMAs (ratio 0.25
// vs 0.375 for the 64x32 warp tile). fp32 accumulate, 1 CTA/SM.
// C(OutT) = A @ B^T [+ bias(f32)] [+ resid(f32)], optional ReLU.
// ---------------------------------------------------------------------------
template<bool RELU, bool RESID, typename OutT>
__global__ void __launch_bounds__(256)
gemm16(const __half* __restrict__ A, int lda,
       const __half* __restrict__ B, int ldb,
       const float* __restrict__ bias,
       const float* __restrict__ resid,
       OutT* __restrict__ C, int ldc,
       int M, int N, int K)
{
    extern __shared__ __half smem[];
    constexpr int STAGE  = 3 * 128 * 64;     // halves per stage: A(128x64)+B(256x64)
    constexpr int B_OFF  = 128 * 64;         // B tile offset within stage (halves)

    const int tid  = threadIdx.x;
    const int warp = tid >> 5, lane = tid & 31;
    const int wm = warp >> 2;                // 0..1  (64-row slab)
    const int wn = warp & 3;                 // 0..3  (64-col slab)
    const int row0 = blockIdx.y * 128;
    const int col0 = blockIdx.x * 256;

    auto load = [&](int stg, int k0) {
        uint32_t as = smem_u32(smem + stg * STAGE);
        uint32_t bs = smem_u32(smem + stg * STAGE + B_OFF);
        // A: 128 rows x 8 chunks = 1024 -> 4 per thread
        #pragma unroll
        for (int i = 0; i < 4; i++) {
            int linear = i * 256 + tid;
            int r = linear >> 3, c16 = linear & 7;
            CP_ASYNC16(as + swz(r, c16), A + (long)(row0 + r) * lda + k0 + c16 * 8);
        }
        // B: 256 rows x 8 chunks = 2048 -> 8 per thread
        #pragma unroll
        for (int i = 0; i < 8; i++) {
            int linear = i * 256 + tid;
            int r = linear >> 3, c16 = linear & 7;
            CP_ASYNC16(bs + swz(r, c16), B + (long)(col0 + r) * ldb + k0 + c16 * 8);
        }
    };

    float acc[4][8][4];
    #pragma unroll
    for (int mt = 0; mt < 4; mt++)
        #pragma unroll
        for (int nt = 0; nt < 8; nt++)
            #pragma unroll
            for (int r = 0; r < 4; r++) acc[mt][nt][r] = 0.0f;

    const int NSTEP = K / 64;
    load(0, 0);  CP_COMMIT;
    load(1, 64); CP_COMMIT;

    for (int t = 0; t < NSTEP; t++) {
        if (t < NSTEP - 1) { CP_WAIT1; } else { CP_WAIT0; }
        __syncthreads();
        if (t + 2 < NSTEP) { load((t + 2) % 3, (t + 2) * 64); CP_COMMIT; }

        const uint32_t as = smem_u32(smem + (t % 3) * STAGE);
        const uint32_t bs = smem_u32(smem + (t % 3) * STAGE + B_OFF);

        #pragma unroll
        for (int ks = 0; ks < 4; ks++) {
            uint32_t a[4][4], br[4][4];
            #pragma unroll
            for (int mt = 0; mt < 4; mt++) {
                int row = wm * 64 + mt * 16 + (lane & 15);
                uint32_t addr = as + swz(row, ks * 2 + (lane >> 4));
                LDMX4(a[mt][0], a[mt][1], a[mt][2], a[mt][3], addr);
            }
            #pragma unroll
            for (int nt2 = 0; nt2 < 4; nt2++) {
                int row = wn * 64 + nt2 * 16 + (lane & 15);
                uint32_t addr = bs + swz(row, ks * 2 + (lane >> 4));
                LDMX4(br[nt2][0], br[nt2][1], br[nt2][2], br[nt2][3], addr);
            }
            #pragma unroll
            for (int mt = 0; mt < 4; mt++)
                #pragma unroll
                for (int nt = 0; nt < 8; nt++) {
                    uint32_t b0 = br[nt >> 1][(nt & 1)];
                    uint32_t b1 = br[nt >> 1][(nt & 1) + 2];
                    MMA16816(acc[mt][nt], a[mt], b0, b1);
                }
        }
    }

    #pragma unroll
    for (int mt = 0; mt < 4; mt++) {
        int r0w = row0 + wm * 64 + mt * 16 + (lane >> 2);
        #pragma unroll
        for (int nt = 0; nt < 8; nt++) {
            int cn = col0 + wn * 64 + nt * 8 + 2 * (lane & 3);
            float v0 = acc[mt][nt][0], v1 = acc[mt][nt][1];
            float v2 = acc[mt][nt][2], v3 = acc[mt][nt][3];
            if (bias) {
                float b0v = bias[cn], b1v = bias[cn + 1];
                v0 += b0v; v1 += b1v; v2 += b0v; v3 += b1v;
            }
            if (RESID) {
                v0 += resid[(long)r0w * ldc + cn];
                v1 += resid[(long)r0w * ldc + cn + 1];
                v2 += resid[(long)(r0w + 8) * ldc + cn];
                v3 += resid[(long)(r0w + 8) * ldc + cn + 1];
            }
            if (RELU) {
                v0 = fmaxf(v0, 0.0f); v1 = fmaxf(v1, 0.0f);
                v2 = fmaxf(v2, 0.0f); v3 = fmaxf(v3, 0.0f);
            }
            store2(C, (long)r0w * ldc + cn, v0, v1);
            store2(C, (long)(r0w + 8) * ldc + cn, v2, v3);
        }
    }
}

// ---------------------------------------------------------------------------
// Flash attention (R11/R13-proven, unchanged): mma.sync, cp.async, swizzle,
// ldmatrix.trans V, double-buffered K/V. Packed-QKV input stride lda.
// ---------------------------------------------------------------------------
__global__ void __launch_bounds__(128)
flash_hmma(const __half* __restrict__ Q, const __half* __restrict__ K,
           const __half* __restrict__ V, int lda, __half* __restrict__ O)
{
    __shared__ __align__(16) union SmemU {
        __half q[128 * 64];
        struct { __half k[2][64 * 64]; __half v[2][64 * 64]; } s;
    } sm;

    const int bh = blockIdx.y;
    const int b  = bh / NH, h = bh % NH;
    const int q0 = blockIdx.x * 128;
    const long baseIn  = (long)b * SQ * lda + (long)h * DH;
    const long baseOut = (long)b * SQ * DM  + (long)h * DH;

    const int tid  = threadIdx.x;
    const int warp = tid >> 5, lane = tid & 31;

    {
        uint32_t qs = smem_u32(sm.q);
        #pragma unroll
        for (int i = 0; i < 8; i++) {
            int linear = i * 128 + tid;
            int r = linear >> 3, c16 = linear & 7;
            CP_ASYNC16(qs + swz(r, c16),
                       Q + baseIn + (long)(q0 + r) * lda + c16 * 8);
        }
        CP_COMMIT; CP_WAIT0;
        __syncthreads();
    }

    uint32_t qf[2][4][4];
    {
        uint32_t qs = smem_u32(sm.q);
        #pragma unroll
        for (int rt = 0; rt < 2; rt++)
            #pragma unroll
            for (int kc = 0; kc < 4; kc++) {
                int row = warp * 32 + rt * 16 + (lane & 15);
                uint32_t addr = qs + swz(row, kc * 2 + (lane >> 4));
                LDMX4(qf[rt][kc][0], qf[rt][kc][1], qf[rt][kc][2], qf[rt][kc][3], addr);
            }
    }
    __syncthreads();

    float o[2][8][4];
    #pragma unroll
    for (int rt = 0; rt < 2; rt++)
        #pragma unroll
        for (int nt = 0; nt < 8; nt++)
            #pragma unroll
            for (int r = 0; r < 4; r++) o[rt][nt][r] = 0.0f;
    float m_lo[2] = {-3.0e38f, -3.0e38f}, m_hi[2] = {-3.0e38f, -3.0e38f};
    float l_lo[2] = {0.0f, 0.0f},         l_hi[2] = {0.0f, 0.0f};

    auto kvload = [&](int stg, int c0) {
        uint32_t ks = smem_u32(sm.s.k[stg]);
        uint32_t vs = smem_u32(sm.s.v[stg]);
        #pragma unroll
        for (int i = 0; i < 4; i++) {
            int linear = i * 128 + tid;
            int r = linear >> 3, c16 = linear & 7;
            CP_ASYNC16(ks + swz(r, c16), K + baseIn + (long)(c0 + r) * lda + c16 * 8);
        }
        #pragma unroll
        for (int i = 0; i < 4; i++) {
            int linear = i * 128 + tid;
            int r = linear >> 3, c16 = linear & 7;
            CP_ASYNC16(vs + swz(r, c16), V + baseIn + (long)(c0 + r) * lda + c16 * 8);
        }
    };

    kvload(0, 0);
    CP_COMMIT;

    const int NT = SQ / 64;
    for (int t = 0; t < NT; t++) {
        if (t + 1 < NT) { kvload((t + 1) & 1, (t + 1) * 64); CP_COMMIT; CP_WAIT1; }
        else            { CP_WAIT0; }
        __syncthreads();

        const uint32_t ks = smem_u32(sm.s.k[t & 1]);
        const uint32_t vs = smem_u32(sm.s.v[t & 1]);

        float s[2][8][4];
        #pragma unroll
        for (int rt = 0; rt < 2; rt++)
            #pragma unroll
            for (int nt = 0; nt < 8; nt++)
                #pragma unroll
                for (int r = 0; r < 4; r++) s[rt][nt][r] = 0.0f;

        #pragma unroll
        for (int kc = 0; kc < 4; kc++) {
            uint32_t br[4][4];
            #pragma unroll
            for (int nt2 = 0; nt2 < 4; nt2++) {
                int row = nt2 * 16 + (lane & 15);
                uint32_t addr = ks + swz(row, kc * 2 + (lane >> 4));
                LDMX4(br[nt2][0], br[nt2][1], br[nt2][2], br[nt2][3], addr);
            }
            #pragma unroll
            for (int rt = 0; rt < 2; rt++)
                #pragma unroll
                for (int nt = 0; nt < 8; nt++)
                    MMA16816(s[rt][nt], qf[rt][kc],
                             br[nt >> 1][nt & 1], br[nt >> 1][(nt & 1) + 2]);
        }

        uint32_t pp[2][8][2];
        #pragma unroll
        for (int rt = 0; rt < 2; rt++) {
            float mt_lo = -3.0e38f, mt_hi = -3.0e38f;
            #pragma unroll
            for (int nt = 0; nt < 8; nt++) {
                mt_lo = fmaxf(mt_lo, fmaxf(s[rt][nt][0], s[rt][nt][1]));
                mt_hi = fmaxf(mt_hi, fmaxf(s[rt][nt][2], s[rt][nt][3]));
            }
            mt_lo *= 0.125f; mt_hi *= 0.125f;
            mt_lo = fmaxf(mt_lo, __shfl_xor_sync(0xffffffffu, mt_lo, 1));
            mt_lo = fmaxf(mt_lo, __shfl_xor_sync(0xffffffffu, mt_lo, 2));
            mt_hi = fmaxf(mt_hi, __shfl_xor_sync(0xffffffffu, mt_hi, 1));
            mt_hi = fmaxf(mt_hi, __shfl_xor_sync(0xffffffffu, mt_hi, 2));

            const float mn_lo = fmaxf(m_lo[rt], mt_lo);
            const float mn_hi = fmaxf(m_hi[rt], mt_hi);
            const float corr_lo = __expf(m_lo[rt] - mn_lo);
            const float corr_hi = __expf(m_hi[rt] - mn_hi);
            m_lo[rt] = mn_lo; m_hi[rt] = mn_hi;

            float rs_lo = 0.0f, rs_hi = 0.0f;
            #pragma unroll
            for (int nt = 0; nt < 8; nt++) {
                float p0 = __expf(fmaf(s[rt][nt][0], 0.125f, -mn_lo));
                float p1 = __expf(fmaf(s[rt][nt][1], 0.125f, -mn_lo));
                float p2 = __expf(fmaf(s[rt][nt][2], 0.125f, -mn_hi));
                float p3 = __expf(fmaf(s[rt][nt][3], 0.125f, -mn_hi));
                rs_lo += p0 + p1; rs_hi += p2 + p3;
                __half2 h01 = __floats2half2_rn(p0, p1);
                __half2 h23 = __floats2half2_rn(p2, p3);
                pp[rt][nt][0] = *(uint32_t*)&h01;
                pp[rt][nt][1] = *(uint32_t*)&h23;
            }
            rs_lo += __shfl_xor_sync(0xffffffffu, rs_lo, 1);
            rs_lo += __shfl_xor_sync(0xffffffffu, rs_lo, 2);
            rs_hi += __shfl_xor_sync(0xffffffffu, rs_hi, 1);
            rs_hi += __shfl_xor_sync(0xffffffffu, rs_hi, 2);
            l_lo[rt] = l_lo[rt] * corr_lo + rs_lo;
            l_hi[rt] = l_hi[rt] * corr_hi + rs_hi;
            #pragma unroll
            for (int nt = 0; nt < 8; nt++) {
                o[rt][nt][0] *= corr_lo; o[rt][nt][1] *= corr_lo;
                o[rt][nt][2] *= corr_hi; o[rt][nt][3] *= corr_hi;
            }
        }

        #pragma unroll
        for (int kc = 0; kc < 4; kc++) {
            uint32_t vr[4][4];
            #pragma unroll
            for (int g2 = 0; g2 < 4; g2++) {
                int row = kc * 16 + (lane & 15);
                uint32_t addr = vs + swz(row, g2 * 2 + (lane >> 4));
                LDMX4T(vr[g2][0], vr[g2][1], vr[g2][2], vr[g2][3], addr);
            }
            #pragma unroll
            for (int rt = 0; rt < 2; rt++) {
                uint32_t a[4] = { pp[rt][2 * kc][0], pp[rt][2 * kc][1],
                                  pp[rt][2 * kc + 1][0], pp[rt][2 * kc + 1][1] };
                #pragma unroll
                for (int nt = 0; nt < 8; nt++)
                    MMA16816(o[rt][nt], a,
                             vr[nt >> 1][(nt & 1) * 2], vr[nt >> 1][(nt & 1) * 2 + 1]);
            }
        }
        __syncthreads();
    }

    #pragma unroll
    for (int rt = 0; rt < 2; rt++) {
        const float inv_lo = 1.0f / l_lo[rt], inv_hi = 1.0f / l_hi[rt];
        const long row_lo = q0 + warp * 32 + rt * 16 + (lane >> 2);
        #pragma unroll
        for (int nt = 0; nt < 8; nt++) {
            int col = nt * 8 + 2 * (lane & 3);
            *(__half2*)&O[baseOut + row_lo * DM + col] =
                __floats2half2_rn(o[rt][nt][0] * inv_lo, o[rt][nt][1] * inv_lo);
            *(__half2*)&O[baseOut + (row_lo + 8) * DM + col] =
                __floats2half2_rn(o[rt][nt][2] * inv_hi, o[rt][nt][3] * inv_hi);
        }
    }
}

// ---------------------------------------------------------------------------
// LayerNorm over rows of length 1024; optional secondary fp16 output.
// ---------------------------------------------------------------------------
template<bool DUAL>
__global__ void __launch_bounds__(256)
layernorm1024(const float* __restrict__ x, const float* __restrict__ g,
              const float* __restrict__ b, float* __restrict__ out,
              __half* __restrict__ out16)
{
    const long row = blockIdx.x;
    const float* p = x + row * (long)DM;
    float v[4];
    float s = 0.0f;
    #pragma unroll
    for (int i = 0; i < 4; i++) {
        v[i] = p[threadIdx.x + i * 256];
        s += v[i];
    }
    s = block_reduce_sum(s);
    const float mean = s * (1.0f / DM);
    float s2 = 0.0f;
    #pragma unroll
    for (int i = 0; i < 4; i++) {
        float d = v[i] - mean;
        s2 += d * d;
    }
    s2 = block_reduce_sum(s2);
    const float rstd = rsqrtf(s2 * (1.0f / DM) + 1e-5f);
    #pragma unroll
    for (int i = 0; i < 4; i++) {
        int c = threadIdx.x + i * 256;
        float y = (v[i] - mean) * rstd * g[c] + b[c];
        out[row * (long)DM + c] = y;
        if (DUAL) out16[row * (long)DM + c] = __float2half(y);
    }
}

// ---------------------------------------------------------------------------
// Launch orchestration (graph-capturable: kernel launches only)
// ---------------------------------------------------------------------------
extern "C" void kernel_launch(void* const* d_in, const int* in_sizes, int n_in,
                              void* d_out, int out_size)
{
    const float* src   = (const float*)d_in[0];
    const float* qw    = (const float*)d_in[1];
    const float* qb    = (const float*)d_in[2];
    const float* kw    = (const float*)d_in[3];
    const float* kb    = (const float*)d_in[4];
    const float* vw    = (const float*)d_in[5];
    const float* vb    = (const float*)d_in[6];
    const float* ow    = (const float*)d_in[7];
    const float* ob    = (const float*)d_in[8];
    const float* w1    = (const float*)d_in[9];
    const float* b1    = (const float*)d_in[10];
    const float* w2    = (const float*)d_in[11];
    const float* b2    = (const float*)d_in[12];
    const float* g1    = (const float*)d_in[13];
    const float* beta1 = (const float*)d_in[14];
    const float* g2    = (const float*)d_in[15];
    const float* beta2 = (const float*)d_in[16];
    float* out = (float*)d_out;

    __half *srch, *wqkvh, *owh, *w1h, *w2h, *qkvh, *ctxh, *x1h, *ffh;
    float  *bqkv, *t0, *t1, *t2;
    cudaGetSymbolAddress((void**)&srch,  g_srch);
    cudaGetSymbolAddress((void**)&wqkvh, g_wqkvh);
    cudaGetSymbolAddress((void**)&bqkv,  g_bqkv);
    cudaGetSymbolAddress((void**)&owh,   g_owh);
    cudaGetSymbolAddress((void**)&w1h,   g_w1h);
    cudaGetSymbolAddress((void**)&w2h,   g_w2h);
    cudaGetSymbolAddress((void**)&qkvh,  g_qkvh);
    cudaGetSymbolAddress((void**)&ctxh,  g_ctxh);
    cudaGetSymbolAddress((void**)&x1h,   g_x1h);
    cudaGetSymbolAddress((void**)&ffh,   g_ffh);
    cudaGetSymbolAddress((void**)&t0,    g_t0);
    cudaGetSymbolAddress((void**)&t1,    g_t1);
    cudaGetSymbolAddress((void**)&t2,    g_t2);

    // 144 KB dynamic smem for 3-stage 128x256 tiles (host-side, capture-safe)
    const int SMEM = 3 * 48 * 1024;
    cudaFuncSetAttribute(gemm16<false,false,__half>,
                         cudaFuncAttributeMaxDynamicSharedMemorySize, SMEM);
    cudaFuncSetAttribute(gemm16<false,true,float>,
                         cudaFuncAttributeMaxDynamicSharedMemorySize, SMEM);
    cudaFuncSetAttribute(gemm16<true,false,__half>,
                         cudaFuncAttributeMaxDynamicSharedMemorySize, SMEM);

    const dim3 blk(256);

    // ---- one-shot conversions
    convert_all<<<16384, blk>>>(src, qw, kw, vw, ow, w1, w2,
                                srch, wqkvh, owh, w1h, w2h);
    pack_bias<<<12, blk>>>(qb, kb, vb, bqkv);

    // ---- fused QKV projection: qkv[4096, 3072] = srch @ wqkv^T + bqkv
    {
        dim3 g(3 * DM / 256, MROWS / 128);
        gemm16<false,false,__half><<<g, blk, SMEM>>>(
            srch, DM, wqkvh, DM, bqkv, nullptr, qkvh, 3 * DM, MROWS, 3 * DM, DM);
    }

    // ---- fused attention on packed QKV (lda = 3*DM); ctxh fp16 out
    {
        dim3 g(SQ / 128, BZ * NH);
        flash_hmma<<<g, dim3(128)>>>(qkvh, qkvh + DM, qkvh + 2 * DM, 3 * DM, ctxh);
    }

    // ---- O projection + residual: y(t1) = ctxh @ ow^T + ob + src
    {
        dim3 g(DM / 256, MROWS / 128);
        gemm16<false,true,float><<<g, blk, SMEM>>>(
            ctxh, DM, owh, DM, ob, src, t1, DM, MROWS, DM, DM);
    }

    // ---- LN1: x1 = LN(y) -> f32 (t2) + fp16 (x1h)
    layernorm1024<true><<<MROWS, blk>>>(t1, g1, beta1, t2, x1h);

    // ---- FF1: ffh = relu(x1h @ w1h^T + b1) (fp16 out)
    {
        dim3 g(FFD / 256, MROWS / 128);
        gemm16<true,false,__half><<<g, blk, SMEM>>>(
            x1h, DM, w1h, DM, b1, nullptr, ffh, FFD, MROWS, FFD, DM);
    }

    // ---- FF2 + residual: y2(t0) = ffh @ w2h^T + b2 + x1(t2)
    {
        dim3 g(DM / 256, MROWS / 128);
        gemm16<false,true,float><<<g, blk, SMEM>>>(
            ffh, FFD, w2h, FFD, b2, t2, t0, DM, MROWS, DM, FFD);
    }

    // ---- LN2 -> output
    layernorm1024<false><<<MROWS, blk>>>(t0, g2, beta2, out, nullptr);
}

// round 16
// speedup vs baseline: 1.1013x; 1.1013x over previous
#include <cuda_runtime.h>
#include <cuda_fp16.h>
#include <cstdint>

// ---------------------------------------------------------------------------
// Problem constants
// ---------------------------------------------------------------------------
#define BZ   2
#define SQ   2048
#define DM   1024
#define NH   16
#define DH   64
#define FFD  4096
#define MROWS (BZ * SQ)            // 4096

// ---------------------------------------------------------------------------
// Scratch (device globals).
// ---------------------------------------------------------------------------
__device__ __half g_srch [(size_t)MROWS * DM];
__device__ __half g_wqkvh[(size_t)3 * DM * DM];
__device__ float  g_bqkv [(size_t)3 * DM];
__device__ __half g_owh  [(size_t)DM * DM];
__device__ __half g_w1h  [(size_t)FFD * DM];
__device__ __half g_w2h  [(size_t)DM * FFD];
__device__ __half g_qkvh [(size_t)MROWS * 3 * DM];
__device__ __half g_ctxh [(size_t)MROWS * DM];
__device__ __half g_x1h  [(size_t)MROWS * DM];
__device__ __half g_ffh  [(size_t)MROWS * FFD];
__device__ float  g_t1   [(size_t)MROWS * DM];
__device__ float  g_t2   [(size_t)MROWS * DM];
__device__ float  g_t0   [(size_t)MROWS * DM];

// ---------------------------------------------------------------------------
// Helpers
// ---------------------------------------------------------------------------
__device__ __forceinline__ uint32_t smem_u32(const void* p) {
    return (uint32_t)__cvta_generic_to_shared(p);
}

#define LDMX4(r0, r1, r2, r3, addr)                                         \
    asm volatile("ldmatrix.sync.aligned.m8n8.x4.shared.b16 {%0,%1,%2,%3}, [%4];" \
                 : "=r"(r0), "=r"(r1), "=r"(r2), "=r"(r3) : "r"(addr))

#define LDMX4T(r0, r1, r2, r3, addr)                                        \
    asm volatile("ldmatrix.sync.aligned.m8n8.x4.trans.shared.b16 {%0,%1,%2,%3}, [%4];" \
                 : "=r"(r0), "=r"(r1), "=r"(r2), "=r"(r3) : "r"(addr))

#define MMA16816(d, a, b0, b1)                                              \
    asm volatile("mma.sync.aligned.m16n8k16.row.col.f32.f16.f16.f32 "        \
                 "{%0,%1,%2,%3}, {%4,%5,%6,%7}, {%8,%9}, {%0,%1,%2,%3};"     \
                 : "+f"(d[0]), "+f"(d[1]), "+f"(d[2]), "+f"(d[3])            \
                 : "r"(a[0]), "r"(a[1]), "r"(a[2]), "r"(a[3]),               \
                   "r"(b0), "r"(b1))

#define CP_ASYNC16(dst, src)                                                \
    asm volatile("cp.async.cg.shared.global [%0], [%1], 16;"                 \
                 :: "r"(dst), "l"(src))
#define CP_COMMIT  asm volatile("cp.async.commit_group;")
#define CP_WAIT0   asm volatile("cp.async.wait_group 0;")
#define CP_WAIT1   asm volatile("cp.async.wait_group 1;")

// swizzled byte offset within a 64-half-wide (128B) row tile
__device__ __forceinline__ uint32_t swz(int r, int c16) {
    return (uint32_t)(r * 128 + ((c16 ^ (r & 7)) * 16));
}

__device__ __forceinline__ void store2(float* C, long idx, float v0, float v1) {
    *(float2*)&C[idx] = make_float2(v0, v1);
}
__device__ __forceinline__ void store2(__half* C, long idx, float v0, float v1) {
    *(__half2*)&C[idx] = __floats2half2_rn(v0, v1);
}

__device__ __forceinline__ float block_reduce_sum(float v) {
    __shared__ float sh[32];
    const unsigned mask = 0xffffffffu;
    #pragma unroll
    for (int o = 16; o > 0; o >>= 1) v += __shfl_xor_sync(mask, v, o);
    int lane = threadIdx.x & 31, w = threadIdx.x >> 5;
    __syncthreads();
    if (lane == 0) sh[w] = v;
    __syncthreads();
    int nw = (blockDim.x + 31) >> 5;
    if (w == 0) {
        v = (lane < nw) ? sh[lane] : 0.0f;
        #pragma unroll
        for (int o = 16; o > 0; o >>= 1) v += __shfl_xor_sync(mask, v, o);
        if (lane == 0) sh[0] = v;
    }
    __syncthreads();
    return sh[0];
}

// ---------------------------------------------------------------------------
// One-shot segmented f32 -> f16 conversion (src + weights); bias pack.
// ---------------------------------------------------------------------------
__global__ void __launch_bounds__(256)
convert_all(const float* __restrict__ src, const float* __restrict__ qw,
            const float* __restrict__ kw,  const float* __restrict__ vw,
            const float* __restrict__ ow,  const float* __restrict__ w1,
            const float* __restrict__ w2,
            __half* __restrict__ srch, __half* __restrict__ wqkv,
            __half* __restrict__ owh,  __half* __restrict__ w1h,
            __half* __restrict__ w2h)
{
    long i = ((long)blockIdx.x * 256 + threadIdx.x) * 4;
    const float* in; __half* out; long off;
    if      (i <  4194304L) { in = src; out = srch;           off = i; }
    else if (i <  5242880L) { in = qw;  out = wqkv;           off = i - 4194304L; }
    else if (i <  6291456L) { in = kw;  out = wqkv + 1048576; off = i - 5242880L; }
    else if (i <  7340032L) { in = vw;  out = wqkv + 2097152; off = i - 6291456L; }
    else if (i <  8388608L) { in = ow;  out = owh;            off = i - 7340032L; }
    else if (i < 12582912L) { in = w1;  out = w1h;            off = i - 8388608L; }
    else                    { in = w2;  out = w2h;            off = i - 12582912L; }
    float4 t = *(const float4*)&in[off];
    __half2* d = (__half2*)&out[off];
    d[0] = __floats2half2_rn(t.x, t.y);
    d[1] = __floats2half2_rn(t.z, t.w);
}

__global__ void __launch_bounds__(256)
pack_bias(const float* __restrict__ qb, const float* __restrict__ kb,
          const float* __restrict__ vb, float* __restrict__ out)
{
    int i = blockIdx.x * 256 + threadIdx.x;
    float v = (i < 1024) ? qb[i] : (i < 2048 ? kb[i - 1024] : vb[i - 2048]);
    out[i] = v;
}

// ---------------------------------------------------------------------------
// Pipelined fp16 GEMM (TN) v3: block tile 128x128x64, FOUR warps (128 thr),
// warp tile 64x64 (2m x 2n). Per 16-K step a warp issues 8 LDMX4 for 32 MMAs
// (ratio 0.25; R13 was 0.375) while smem stays 96 KB (3 stages x 32 KB) so
// TWO CTAs fit per SM (2 x 128 x 255 regs = 65280 <= 65536). Single
// __syncthreads per iter. fp32 accumulate.
// C(OutT) = A @ B^T [+ bias(f32)] [+ resid(f32)], optional ReLU.
// ---------------------------------------------------------------------------
template<bool RELU, bool RESID, typename OutT>
__global__ void __launch_bounds__(128)
gemm16(const __half* __restrict__ A, int lda,
       const __half* __restrict__ B, int ldb,
       const float* __restrict__ bias,
       const float* __restrict__ resid,
       OutT* __restrict__ C, int ldc,
       int M, int N, int K)
{
    extern __shared__ __half smem[];
    constexpr int STAGE = 2 * 128 * 64;      // halves per stage (A + B tiles)
    constexpr int B_OFF = 128 * 64;

    const int tid  = threadIdx.x;
    const int warp = tid >> 5, lane = tid & 31;
    const int wm = warp >> 1;                // 0..1 (64-row slab)
    const int wn = warp & 1;                 // 0..1 (64-col slab)
    const int row0 = blockIdx.y * 128;
    const int col0 = blockIdx.x * 128;

    auto load = [&](int stg, int k0) {
        uint32_t as = smem_u32(smem + stg * STAGE);
        uint32_t bs = smem_u32(smem + stg * STAGE + B_OFF);
        #pragma unroll
        for (int i = 0; i < 8; i++) {
            int linear = i * 128 + tid;
            int r = linear >> 3, c16 = linear & 7;
            CP_ASYNC16(as + swz(r, c16), A + (long)(row0 + r) * lda + k0 + c16 * 8);
        }
        #pragma unroll
        for (int i = 0; i < 8; i++) {
            int linear = i * 128 + tid;
            int r = linear >> 3, c16 = linear & 7;
            CP_ASYNC16(bs + swz(r, c16), B + (long)(col0 + r) * ldb + k0 + c16 * 8);
        }
    };

    float acc[4][8][4];
    #pragma unroll
    for (int mt = 0; mt < 4; mt++)
        #pragma unroll
        for (int nt = 0; nt < 8; nt++)
            #pragma unroll
            for (int r = 0; r < 4; r++) acc[mt][nt][r] = 0.0f;

    const int NSTEP = K / 64;
    load(0, 0);  CP_COMMIT;
    load(1, 64); CP_COMMIT;

    for (int t = 0; t < NSTEP; t++) {
        if (t < NSTEP - 1) { CP_WAIT1; } else { CP_WAIT0; }
        __syncthreads();
        if (t + 2 < NSTEP) { load((t + 2) % 3, (t + 2) * 64); CP_COMMIT; }

        const uint32_t as = smem_u32(smem + (t % 3) * STAGE);
        const uint32_t bs = smem_u32(smem + (t % 3) * STAGE + B_OFF);

        #pragma unroll
        for (int ks = 0; ks < 4; ks++) {
            uint32_t a[4][4], br[4][4];
            #pragma unroll
            for (int mt = 0; mt < 4; mt++) {
                int row = wm * 64 + mt * 16 + (lane & 15);
                uint32_t addr = as + swz(row, ks * 2 + (lane >> 4));
                LDMX4(a[mt][0], a[mt][1], a[mt][2], a[mt][3], addr);
            }
            #pragma unroll
            for (int nt2 = 0; nt2 < 4; nt2++) {
                int row = wn * 64 + nt2 * 16 + (lane & 15);
                uint32_t addr = bs + swz(row, ks * 2 + (lane >> 4));
                LDMX4(br[nt2][0], br[nt2][1], br[nt2][2], br[nt2][3], addr);
            }
            #pragma unroll
            for (int mt = 0; mt < 4; mt++)
                #pragma unroll
                for (int nt = 0; nt < 8; nt++) {
                    uint32_t b0 = br[nt >> 1][(nt & 1)];
                    uint32_t b1 = br[nt >> 1][(nt & 1) + 2];
                    MMA16816(acc[mt][nt], a[mt], b0, b1);
                }
        }
    }

    #pragma unroll
    for (int mt = 0; mt < 4; mt++) {
        int r0w = row0 + wm * 64 + mt * 16 + (lane >> 2);
        #pragma unroll
        for (int nt = 0; nt < 8; nt++) {
            int cn = col0 + wn * 64 + nt * 8 + 2 * (lane & 3);
            float v0 = acc[mt][nt][0], v1 = acc[mt][nt][1];
            float v2 = acc[mt][nt][2], v3 = acc[mt][nt][3];
            if (bias) {
                float b0v = bias[cn], b1v = bias[cn + 1];
                v0 += b0v; v1 += b1v; v2 += b0v; v3 += b1v;
            }
            if (RESID) {
                v0 += resid[(long)r0w * ldc + cn];
                v1 += resid[(long)r0w * ldc + cn + 1];
                v2 += resid[(long)(r0w + 8) * ldc + cn];
                v3 += resid[(long)(r0w + 8) * ldc + cn + 1];
            }
            if (RELU) {
                v0 = fmaxf(v0, 0.0f); v1 = fmaxf(v1, 0.0f);
                v2 = fmaxf(v2, 0.0f); v3 = fmaxf(v3, 0.0f);
            }
            store2(C, (long)r0w * ldc + cn, v0, v1);
            store2(C, (long)(r0w + 8) * ldc + cn, v2, v3);
        }
    }
}

// ---------------------------------------------------------------------------
// Flash attention (R11/R13-proven, unchanged): mma.sync, cp.async, swizzle,
// ldmatrix.trans V, double-buffered K/V. Packed-QKV input stride lda.
// ---------------------------------------------------------------------------
__global__ void __launch_bounds__(128)
flash_hmma(const __half* __restrict__ Q, const __half* __restrict__ K,
           const __half* __restrict__ V, int lda, __half* __restrict__ O)
{
    __shared__ __align__(16) union SmemU {
        __half q[128 * 64];
        struct { __half k[2][64 * 64]; __half v[2][64 * 64]; } s;
    } sm;

    const int bh = blockIdx.y;
    const int b  = bh / NH, h = bh % NH;
    const int q0 = blockIdx.x * 128;
    const long baseIn  = (long)b * SQ * lda + (long)h * DH;
    const long baseOut = (long)b * SQ * DM  + (long)h * DH;

    const int tid  = threadIdx.x;
    const int warp = tid >> 5, lane = tid & 31;

    {
        uint32_t qs = smem_u32(sm.q);
        #pragma unroll
        for (int i = 0; i < 8; i++) {
            int linear = i * 128 + tid;
            int r = linear >> 3, c16 = linear & 7;
            CP_ASYNC16(qs + swz(r, c16),
                       Q + baseIn + (long)(q0 + r) * lda + c16 * 8);
        }
        CP_COMMIT; CP_WAIT0;
        __syncthreads();
    }

    uint32_t qf[2][4][4];
    {
        uint32_t qs = smem_u32(sm.q);
        #pragma unroll
        for (int rt = 0; rt < 2; rt++)
            #pragma unroll
            for (int kc = 0; kc < 4; kc++) {
                int row = warp * 32 + rt * 16 + (lane & 15);
                uint32_t addr = qs + swz(row, kc * 2 + (lane >> 4));
                LDMX4(qf[rt][kc][0], qf[rt][kc][1], qf[rt][kc][2], qf[rt][kc][3], addr);
            }
    }
    __syncthreads();

    float o[2][8][4];
    #pragma unroll
    for (int rt = 0; rt < 2; rt++)
        #pragma unroll
        for (int nt = 0; nt < 8; nt++)
            #pragma unroll
            for (int r = 0; r < 4; r++) o[rt][nt][r] = 0.0f;
    float m_lo[2] = {-3.0e38f, -3.0e38f}, m_hi[2] = {-3.0e38f, -3.0e38f};
    float l_lo[2] = {0.0f, 0.0f},         l_hi[2] = {0.0f, 0.0f};

    auto kvload = [&](int stg, int c0) {
        uint32_t ks = smem_u32(sm.s.k[stg]);
        uint32_t vs = smem_u32(sm.s.v[stg]);
        #pragma unroll
        for (int i = 0; i < 4; i++) {
            int linear = i * 128 + tid;
            int r = linear >> 3, c16 = linear & 7;
            CP_ASYNC16(ks + swz(r, c16), K + baseIn + (long)(c0 + r) * lda + c16 * 8);
        }
        #pragma unroll
        for (int i = 0; i < 4; i++) {
            int linear = i * 128 + tid;
            int r = linear >> 3, c16 = linear & 7;
            CP_ASYNC16(vs + swz(r, c16), V + baseIn + (long)(c0 + r) * lda + c16 * 8);
        }
    };

    kvload(0, 0);
    CP_COMMIT;

    const int NT = SQ / 64;
    for (int t = 0; t < NT; t++) {
        if (t + 1 < NT) { kvload((t + 1) & 1, (t + 1) * 64); CP_COMMIT; CP_WAIT1; }
        else            { CP_WAIT0; }
        __syncthreads();

        const uint32_t ks = smem_u32(sm.s.k[t & 1]);
        const uint32_t vs = smem_u32(sm.s.v[t & 1]);

        float s[2][8][4];
        #pragma unroll
        for (int rt = 0; rt < 2; rt++)
            #pragma unroll
            for (int nt = 0; nt < 8; nt++)
                #pragma unroll
                for (int r = 0; r < 4; r++) s[rt][nt][r] = 0.0f;

        #pragma unroll
        for (int kc = 0; kc < 4; kc++) {
            uint32_t br[4][4];
            #pragma unroll
            for (int nt2 = 0; nt2 < 4; nt2++) {
                int row = nt2 * 16 + (lane & 15);
                uint32_t addr = ks + swz(row, kc * 2 + (lane >> 4));
                LDMX4(br[nt2][0], br[nt2][1], br[nt2][2], br[nt2][3], addr);
            }
            #pragma unroll
            for (int rt = 0; rt < 2; rt++)
                #pragma unroll
                for (int nt = 0; nt < 8; nt++)
                    MMA16816(s[rt][nt], qf[rt][kc],
                             br[nt >> 1][nt & 1], br[nt >> 1][(nt & 1) + 2]);
        }

        uint32_t pp[2][8][2];
        #pragma unroll
        for (int rt = 0; rt < 2; rt++) {
            float mt_lo = -3.0e38f, mt_hi = -3.0e38f;
            #pragma unroll
            for (int nt = 0; nt < 8; nt++) {
                mt_lo = fmaxf(mt_lo, fmaxf(s[rt][nt][0], s[rt][nt][1]));
                mt_hi = fmaxf(mt_hi, fmaxf(s[rt][nt][2], s[rt][nt][3]));
            }
            mt_lo *= 0.125f; mt_hi *= 0.125f;
            mt_lo = fmaxf(mt_lo, __shfl_xor_sync(0xffffffffu, mt_lo, 1));
            mt_lo = fmaxf(mt_lo, __shfl_xor_sync(0xffffffffu, mt_lo, 2));
            mt_hi = fmaxf(mt_hi, __shfl_xor_sync(0xffffffffu, mt_hi, 1));
            mt_hi = fmaxf(mt_hi, __shfl_xor_sync(0xffffffffu, mt_hi, 2));

            const float mn_lo = fmaxf(m_lo[rt], mt_lo);
            const float mn_hi = fmaxf(m_hi[rt], mt_hi);
            const float corr_lo = __expf(m_lo[rt] - mn_lo);
            const float corr_hi = __expf(m_hi[rt] - mn_hi);
            m_lo[rt] = mn_lo; m_hi[rt] = mn_hi;

            float rs_lo = 0.0f, rs_hi = 0.0f;
            #pragma unroll
            for (int nt = 0; nt < 8; nt++) {
                float p0 = __expf(fmaf(s[rt][nt][0], 0.125f, -mn_lo));
                float p1 = __expf(fmaf(s[rt][nt][1], 0.125f, -mn_lo));
                float p2 = __expf(fmaf(s[rt][nt][2], 0.125f, -mn_hi));
                float p3 = __expf(fmaf(s[rt][nt][3], 0.125f, -mn_hi));
                rs_lo += p0 + p1; rs_hi += p2 + p3;
                __half2 h01 = __floats2half2_rn(p0, p1);
                __half2 h23 = __floats2half2_rn(p2, p3);
                pp[rt][nt][0] = *(uint32_t*)&h01;
                pp[rt][nt][1] = *(uint32_t*)&h23;
            }
            rs_lo += __shfl_xor_sync(0xffffffffu, rs_lo, 1);
            rs_lo += __shfl_xor_sync(0xffffffffu, rs_lo, 2);
            rs_hi += __shfl_xor_sync(0xffffffffu, rs_hi, 1);
            rs_hi += __shfl_xor_sync(0xffffffffu, rs_hi, 2);
            l_lo[rt] = l_lo[rt] * corr_lo + rs_lo;
            l_hi[rt] = l_hi[rt] * corr_hi + rs_hi;
            #pragma unroll
            for (int nt = 0; nt < 8; nt++) {
                o[rt][nt][0] *= corr_lo; o[rt][nt][1] *= corr_lo;
                o[rt][nt][2] *= corr_hi; o[rt][nt][3] *= corr_hi;
            }
        }

        #pragma unroll
        for (int kc = 0; kc < 4; kc++) {
            uint32_t vr[4][4];
            #pragma unroll
            for (int g2 = 0; g2 < 4; g2++) {
                int row = kc * 16 + (lane & 15);
                uint32_t addr = vs + swz(row, g2 * 2 + (lane >> 4));
                LDMX4T(vr[g2][0], vr[g2][1], vr[g2][2], vr[g2][3], addr);
            }
            #pragma unroll
            for (int rt = 0; rt < 2; rt++) {
                uint32_t a[4] = { pp[rt][2 * kc][0], pp[rt][2 * kc][1],
                                  pp[rt][2 * kc + 1][0], pp[rt][2 * kc + 1][1] };
                #pragma unroll
                for (int nt = 0; nt < 8; nt++)
                    MMA16816(o[rt][nt], a,
                             vr[nt >> 1][(nt & 1) * 2], vr[nt >> 1][(nt & 1) * 2 + 1]);
            }
        }
        __syncthreads();
    }

    #pragma unroll
    for (int rt = 0; rt < 2; rt++) {
        const float inv_lo = 1.0f / l_lo[rt], inv_hi = 1.0f / l_hi[rt];
        const long row_lo = q0 + warp * 32 + rt * 16 + (lane >> 2);
        #pragma unroll
        for (int nt = 0; nt < 8; nt++) {
            int col = nt * 8 + 2 * (lane & 3);
            *(__half2*)&O[baseOut + row_lo * DM + col] =
                __floats2half2_rn(o[rt][nt][0] * inv_lo, o[rt][nt][1] * inv_lo);
            *(__half2*)&O[baseOut + (row_lo + 8) * DM + col] =
                __floats2half2_rn(o[rt][nt][2] * inv_hi, o[rt][nt][3] * inv_hi);
        }
    }
}

// ---------------------------------------------------------------------------
// LayerNorm over rows of length 1024; optional secondary fp16 output.
// ---------------------------------------------------------------------------
template<bool DUAL>
__global__ void __launch_bounds__(256)
layernorm1024(const float* __restrict__ x, const float* __restrict__ g,
              const float* __restrict__ b, float* __restrict__ out,
              __half* __restrict__ out16)
{
    const long row = blockIdx.x;
    const float* p = x + row * (long)DM;
    float v[4];
    float s = 0.0f;
    #pragma unroll
    for (int i = 0; i < 4; i++) {
        v[i] = p[threadIdx.x + i * 256];
        s += v[i];
    }
    s = block_reduce_sum(s);
    const float mean = s * (1.0f / DM);
    float s2 = 0.0f;
    #pragma unroll
    for (int i = 0; i < 4; i++) {
        float d = v[i] - mean;
        s2 += d * d;
    }
    s2 = block_reduce_sum(s2);
    const float rstd = rsqrtf(s2 * (1.0f / DM) + 1e-5f);
    #pragma unroll
    for (int i = 0; i < 4; i++) {
        int c = threadIdx.x + i * 256;
        float y = (v[i] - mean) * rstd * g[c] + b[c];
        out[row * (long)DM + c] = y;
        if (DUAL) out16[row * (long)DM + c] = __float2half(y);
    }
}

// ---------------------------------------------------------------------------
// Launch orchestration (graph-capturable: kernel launches only)
// ---------------------------------------------------------------------------
extern "C" void kernel_launch(void* const* d_in, const int* in_sizes, int n_in,
                              void* d_out, int out_size)
{
    const float* src   = (const float*)d_in[0];
    const float* qw    = (const float*)d_in[1];
    const float* qb    = (const float*)d_in[2];
    const float* kw    = (const float*)d_in[3];
    const float* kb    = (const float*)d_in[4];
    const float* vw    = (const float*)d_in[5];
    const float* vb    = (const float*)d_in[6];
    const float* ow    = (const float*)d_in[7];
    const float* ob    = (const float*)d_in[8];
    const float* w1    = (const float*)d_in[9];
    const float* b1    = (const float*)d_in[10];
    const float* w2    = (const float*)d_in[11];
    const float* b2    = (const float*)d_in[12];
    const float* g1    = (const float*)d_in[13];
    const float* beta1 = (const float*)d_in[14];
    const float* g2    = (const float*)d_in[15];
    const float* beta2 = (const float*)d_in[16];
    float* out = (float*)d_out;

    __half *srch, *wqkvh, *owh, *w1h, *w2h, *qkvh, *ctxh, *x1h, *ffh;
    float  *bqkv, *t0, *t1, *t2;
    cudaGetSymbolAddress((void**)&srch,  g_srch);
    cudaGetSymbolAddress((void**)&wqkvh, g_wqkvh);
    cudaGetSymbolAddress((void**)&bqkv,  g_bqkv);
    cudaGetSymbolAddress((void**)&owh,   g_owh);
    cudaGetSymbolAddress((void**)&w1h,   g_w1h);
    cudaGetSymbolAddress((void**)&w2h,   g_w2h);
    cudaGetSymbolAddress((void**)&qkvh,  g_qkvh);
    cudaGetSymbolAddress((void**)&ctxh,  g_ctxh);
    cudaGetSymbolAddress((void**)&x1h,   g_x1h);
    cudaGetSymbolAddress((void**)&ffh,   g_ffh);
    cudaGetSymbolAddress((void**)&t0,    g_t0);
    cudaGetSymbolAddress((void**)&t1,    g_t1);
    cudaGetSymbolAddress((void**)&t2,    g_t2);

    // 96 KB dynamic smem (3 stages x 32 KB); host-side, capture-safe
    const int SMEM = 96 * 1024;
    cudaFuncSetAttribute(gemm16<false,false,__half>,
                         cudaFuncAttributeMaxDynamicSharedMemorySize, SMEM);
    cudaFuncSetAttribute(gemm16<false,true,float>,
                         cudaFuncAttributeMaxDynamicSharedMemorySize, SMEM);
    cudaFuncSetAttribute(gemm16<true,false,__half>,
                         cudaFuncAttributeMaxDynamicSharedMemorySize, SMEM);

    const dim3 blk(256);
    const dim3 gblk(128);

    // ---- one-shot conversions
    convert_all<<<16384, blk>>>(src, qw, kw, vw, ow, w1, w2,
                                srch, wqkvh, owh, w1h, w2h);
    pack_bias<<<12, blk>>>(qb, kb, vb, bqkv);

    // ---- fused QKV projection: qkv[4096, 3072] = srch @ wqkv^T + bqkv
    {
        dim3 g(3 * DM / 128, MROWS / 128);
        gemm16<false,false,__half><<<g, gblk, SMEM>>>(
            srch, DM, wqkvh, DM, bqkv, nullptr, qkvh, 3 * DM, MROWS, 3 * DM, DM);
    }

    // ---- fused attention on packed QKV (lda = 3*DM); ctxh fp16 out
    {
        dim3 g(SQ / 128, BZ * NH);
        flash_hmma<<<g, dim3(128)>>>(qkvh, qkvh + DM, qkvh + 2 * DM, 3 * DM, ctxh);
    }

    // ---- O projection + residual: y(t1) = ctxh @ ow^T + ob + src
    {
        dim3 g(DM / 128, MROWS / 128);
        gemm16<false,true,float><<<g, gblk, SMEM>>>(
            ctxh, DM, owh, DM, ob, src, t1, DM, MROWS, DM, DM);
    }

    // ---- LN1: x1 = LN(y) -> f32 (t2) + fp16 (x1h)
    layernorm1024<true><<<MROWS, blk>>>(t1, g1, beta1, t2, x1h);

    // ---- FF1: ffh = relu(x1h @ w1h^T + b1) (fp16 out)
    {
        dim3 g(FFD / 128, MROWS / 128);
        gemm16<true,false,__half><<<g, gblk, SMEM>>>(
            x1h, DM, w1h, DM, b1, nullptr, ffh, FFD, MROWS, FFD, DM);
    }

    // ---- FF2 + residual: y2(t0) = ffh @ w2h^T + b2 + x1(t2)
    {
        dim3 g(DM / 128, MROWS / 128);
        gemm16<false,true,float><<<g, gblk, SMEM>>>(
            ffh, FFD, w2h, FFD, b2, t2, t0, DM, MROWS, DM, FFD);
    }

    // ---- LN2 -> output
    layernorm1024<false><<<MROWS, blk>>>(t0, g2, beta2, out, nullptr);
}

// round 17
// speedup vs baseline: 1.1101x; 1.0080x over previous
#include <cuda_runtime.h>
#include <cuda_fp16.h>
#include <cstdint>

// ---------------------------------------------------------------------------
// Problem constants
// ---------------------------------------------------------------------------
#define BZ   2
#define SQ   2048
#define DM   1024
#define NH   16
#define DH   64
#define FFD  4096
#define MROWS (BZ * SQ)            // 4096

// ---------------------------------------------------------------------------
// Scratch (device globals).
// ---------------------------------------------------------------------------
__device__ __half g_srch [(size_t)MROWS * DM];
__device__ __half g_wqkvh[(size_t)3 * DM * DM];
__device__ float  g_bqkv [(size_t)3 * DM];
__device__ __half g_owh  [(size_t)DM * DM];
__device__ __half g_w1h  [(size_t)FFD * DM];
__device__ __half g_w2h  [(size_t)DM * FFD];
__device__ __half g_qkvh [(size_t)MROWS * 3 * DM];
__device__ __half g_ctxh [(size_t)MROWS * DM];
__device__ __half g_x1h  [(size_t)MROWS * DM];
__device__ __half g_ffh  [(size_t)MROWS * FFD];
__device__ float  g_t1   [(size_t)MROWS * DM];
__device__ float  g_t2   [(size_t)MROWS * DM];
__device__ float  g_t0   [(size_t)MROWS * DM];

// ---------------------------------------------------------------------------
// Helpers
// ---------------------------------------------------------------------------
__device__ __forceinline__ uint32_t smem_u32(const void* p) {
    return (uint32_t)__cvta_generic_to_shared(p);
}

#define LDMX4(r0, r1, r2, r3, addr)                                         \
    asm volatile("ldmatrix.sync.aligned.m8n8.x4.shared.b16 {%0,%1,%2,%3}, [%4];" \
                 : "=r"(r0), "=r"(r1), "=r"(r2), "=r"(r3) : "r"(addr))

#define LDMX4T(r0, r1, r2, r3, addr)                                        \
    asm volatile("ldmatrix.sync.aligned.m8n8.x4.trans.shared.b16 {%0,%1,%2,%3}, [%4];" \
                 : "=r"(r0), "=r"(r1), "=r"(r2), "=r"(r3) : "r"(addr))

#define MMA16816(d, a, b0, b1)                                              \
    asm volatile("mma.sync.aligned.m16n8k16.row.col.f32.f16.f16.f32 "        \
                 "{%0,%1,%2,%3}, {%4,%5,%6,%7}, {%8,%9}, {%0,%1,%2,%3};"     \
                 : "+f"(d[0]), "+f"(d[1]), "+f"(d[2]), "+f"(d[3])            \
                 : "r"(a[0]), "r"(a[1]), "r"(a[2]), "r"(a[3]),               \
                   "r"(b0), "r"(b1))

#define CP_ASYNC16(dst, src)                                                \
    asm volatile("cp.async.cg.shared.global [%0], [%1], 16;"                 \
                 :: "r"(dst), "l"(src))
#define CP_COMMIT  asm volatile("cp.async.commit_group;")
#define CP_WAIT0   asm volatile("cp.async.wait_group 0;")
#define CP_WAIT1   asm volatile("cp.async.wait_group 1;")

// swizzled byte offset within a 64-half-wide (128B) row tile
__device__ __forceinline__ uint32_t swz(int r, int c16) {
    return (uint32_t)(r * 128 + ((c16 ^ (r & 7)) * 16));
}

__device__ __forceinline__ void store2(float* C, long idx, float v0, float v1) {
    *(float2*)&C[idx] = make_float2(v0, v1);
}
__device__ __forceinline__ void store2(__half* C, long idx, float v0, float v1) {
    *(__half2*)&C[idx] = __floats2half2_rn(v0, v1);
}

__device__ __forceinline__ float block_reduce_sum(float v) {
    __shared__ float sh[32];
    const unsigned mask = 0xffffffffu;
    #pragma unroll
    for (int o = 16; o > 0; o >>= 1) v += __shfl_xor_sync(mask, v, o);
    int lane = threadIdx.x & 31, w = threadIdx.x >> 5;
    __syncthreads();
    if (lane == 0) sh[w] = v;
    __syncthreads();
    int nw = (blockDim.x + 31) >> 5;
    if (w == 0) {
        v = (lane < nw) ? sh[lane] : 0.0f;
        #pragma unroll
        for (int o = 16; o > 0; o >>= 1) v += __shfl_xor_sync(mask, v, o);
        if (lane == 0) sh[0] = v;
    }
    __syncthreads();
    return sh[0];
}

// ---------------------------------------------------------------------------
// One-shot segmented f32 -> f16 conversion (src + weights); bias pack.
// ---------------------------------------------------------------------------
__global__ void __launch_bounds__(256)
convert_all(const float* __restrict__ src, const float* __restrict__ qw,
            const float* __restrict__ kw,  const float* __restrict__ vw,
            const float* __restrict__ ow,  const float* __restrict__ w1,
            const float* __restrict__ w2,
            __half* __restrict__ srch, __half* __restrict__ wqkv,
            __half* __restrict__ owh,  __half* __restrict__ w1h,
            __half* __restrict__ w2h)
{
    long i = ((long)blockIdx.x * 256 + threadIdx.x) * 4;
    const float* in; __half* out; long off;
    if      (i <  4194304L) { in = src; out = srch;           off = i; }
    else if (i <  5242880L) { in = qw;  out = wqkv;           off = i - 4194304L; }
    else if (i <  6291456L) { in = kw;  out = wqkv + 1048576; off = i - 5242880L; }
    else if (i <  7340032L) { in = vw;  out = wqkv + 2097152; off = i - 6291456L; }
    else if (i <  8388608L) { in = ow;  out = owh;            off = i - 7340032L; }
    else if (i < 12582912L) { in = w1;  out = w1h;            off = i - 8388608L; }
    else                    { in = w2;  out = w2h;            off = i - 12582912L; }
    float4 t = *(const float4*)&in[off];
    __half2* d = (__half2*)&out[off];
    d[0] = __floats2half2_rn(t.x, t.y);
    d[1] = __floats2half2_rn(t.z, t.w);
}

__global__ void __launch_bounds__(256)
pack_bias(const float* __restrict__ qb, const float* __restrict__ kb,
          const float* __restrict__ vb, float* __restrict__ out)
{
    int i = blockIdx.x * 256 + threadIdx.x;
    float v = (i < 1024) ? qb[i] : (i < 2048 ? kb[i - 1024] : vb[i - 2048]);
    out[i] = v;
}

// ---------------------------------------------------------------------------
// Pipelined fp16 GEMM (TN) — R13-proven config: 256 thr, tile 128x128x64,
// warp tile 64x32 (2m x 4n), 3-stage cp.async, ONE syncthreads per iter.
// C(OutT) = A @ B^T [+ bias(f32)] [+ resid(f32)], optional ReLU.
// ---------------------------------------------------------------------------
template<bool RELU, bool RESID, typename OutT>
__global__ void __launch_bounds__(256, 2)
gemm16(const __half* __restrict__ A, int lda,
       const __half* __restrict__ B, int ldb,
       const float* __restrict__ bias,
       const float* __restrict__ resid,
       OutT* __restrict__ C, int ldc,
       int M, int N, int K)
{
    extern __shared__ __half smem[];
    constexpr int STAGE = 2 * 128 * 64;

    const int tid  = threadIdx.x;
    const int warp = tid >> 5, lane = tid & 31;
    const int wm = warp >> 2;
    const int wn = warp & 3;
    const int row0 = blockIdx.y * 128;
    const int col0 = blockIdx.x * 128;

    auto load = [&](int stg, int k0) {
        uint32_t as = smem_u32(smem + stg * STAGE);
        uint32_t bs = smem_u32(smem + stg * STAGE + 128 * 64);
        #pragma unroll
        for (int i = 0; i < 4; i++) {
            int linear = i * 256 + tid;
            int r = linear >> 3, c16 = linear & 7;
            CP_ASYNC16(as + swz(r, c16), A + (long)(row0 + r) * lda + k0 + c16 * 8);
        }
        #pragma unroll
        for (int i = 0; i < 4; i++) {
            int linear = i * 256 + tid;
            int r = linear >> 3, c16 = linear & 7;
            CP_ASYNC16(bs + swz(r, c16), B + (long)(col0 + r) * ldb + k0 + c16 * 8);
        }
    };

    float acc[4][4][4];
    #pragma unroll
    for (int mt = 0; mt < 4; mt++)
        #pragma unroll
        for (int nt = 0; nt < 4; nt++)
            #pragma unroll
            for (int r = 0; r < 4; r++) acc[mt][nt][r] = 0.0f;

    const int NSTEP = K / 64;
    load(0, 0);  CP_COMMIT;
    load(1, 64); CP_COMMIT;

    for (int t = 0; t < NSTEP; t++) {
        if (t < NSTEP - 1) { CP_WAIT1; } else { CP_WAIT0; }
        __syncthreads();
        if (t + 2 < NSTEP) { load((t + 2) % 3, (t + 2) * 64); CP_COMMIT; }

        const uint32_t as = smem_u32(smem + (t % 3) * STAGE);
        const uint32_t bs = smem_u32(smem + (t % 3) * STAGE + 128 * 64);

        #pragma unroll
        for (int ks = 0; ks < 4; ks++) {
            uint32_t a[4][4], br[2][4];
            #pragma unroll
            for (int mt = 0; mt < 4; mt++) {
                int row = wm * 64 + mt * 16 + (lane & 15);
                uint32_t addr = as + swz(row, ks * 2 + (lane >> 4));
                LDMX4(a[mt][0], a[mt][1], a[mt][2], a[mt][3], addr);
            }
            #pragma unroll
            for (int nt2 = 0; nt2 < 2; nt2++) {
                int row = wn * 32 + nt2 * 16 + (lane & 15);
                uint32_t addr = bs + swz(row, ks * 2 + (lane >> 4));
                LDMX4(br[nt2][0], br[nt2][1], br[nt2][2], br[nt2][3], addr);
            }
            #pragma unroll
            for (int mt = 0; mt < 4; mt++)
                #pragma unroll
                for (int nt = 0; nt < 4; nt++) {
                    uint32_t b0 = br[nt >> 1][(nt & 1)];
                    uint32_t b1 = br[nt >> 1][(nt & 1) + 2];
                    MMA16816(acc[mt][nt], a[mt], b0, b1);
                }
        }
    }

    #pragma unroll
    for (int mt = 0; mt < 4; mt++) {
        int r0w = row0 + wm * 64 + mt * 16 + (lane >> 2);
        #pragma unroll
        for (int nt = 0; nt < 4; nt++) {
            int cn = col0 + wn * 32 + nt * 8 + 2 * (lane & 3);
            float v0 = acc[mt][nt][0], v1 = acc[mt][nt][1];
            float v2 = acc[mt][nt][2], v3 = acc[mt][nt][3];
            if (bias) {
                float b0v = bias[cn], b1v = bias[cn + 1];
                v0 += b0v; v1 += b1v; v2 += b0v; v3 += b1v;
            }
            if (RESID) {
                v0 += resid[(long)r0w * ldc + cn];
                v1 += resid[(long)r0w * ldc + cn + 1];
                v2 += resid[(long)(r0w + 8) * ldc + cn];
                v3 += resid[(long)(r0w + 8) * ldc + cn + 1];
            }
            if (RELU) {
                v0 = fmaxf(v0, 0.0f); v1 = fmaxf(v1, 0.0f);
                v2 = fmaxf(v2, 0.0f); v3 = fmaxf(v3, 0.0f);
            }
            store2(C, (long)r0w * ldc + cn, v0, v1);
            store2(C, (long)(r0w + 8) * ldc + cn, v2, v3);
        }
    }
}

// ---------------------------------------------------------------------------
// Flash attention v4: 3-stage K/V cp.async pipeline, ONE syncthreads per
// tile (stage (t+2)%3 == (t-1)%3 was consumed before the sync at t).
// 128 threads (4 warps x 32 query rows), BR=128, BC=64, swizzled smem,
// ldmatrix.trans V. Packed-QKV input stride lda; fp16 ctx out (stride DM).
// ---------------------------------------------------------------------------
__global__ void __launch_bounds__(128)
flash_hmma(const __half* __restrict__ Q, const __half* __restrict__ K,
           const __half* __restrict__ V, int lda, __half* __restrict__ O)
{
    __shared__ __align__(16) union SmemU {
        __half q[128 * 64];                                  // 16 KB (Q phase)
        struct { __half k[3][64 * 64]; __half v[3][64 * 64]; } s;  // 48 KB
    } sm;

    const int bh = blockIdx.y;
    const int b  = bh / NH, h = bh % NH;
    const int q0 = blockIdx.x * 128;
    const long baseIn  = (long)b * SQ * lda + (long)h * DH;
    const long baseOut = (long)b * SQ * DM  + (long)h * DH;

    const int tid  = threadIdx.x;
    const int warp = tid >> 5, lane = tid & 31;

    // ---- Q tile + fragments (Q smem consumed before stages are filled)
    {
        uint32_t qs = smem_u32(sm.q);
        #pragma unroll
        for (int i = 0; i < 8; i++) {
            int linear = i * 128 + tid;
            int r = linear >> 3, c16 = linear & 7;
            CP_ASYNC16(qs + swz(r, c16),
                       Q + baseIn + (long)(q0 + r) * lda + c16 * 8);
        }
        CP_COMMIT; CP_WAIT0;
        __syncthreads();
    }

    uint32_t qf[2][4][4];
    {
        uint32_t qs = smem_u32(sm.q);
        #pragma unroll
        for (int rt = 0; rt < 2; rt++)
            #pragma unroll
            for (int kc = 0; kc < 4; kc++) {
                int row = warp * 32 + rt * 16 + (lane & 15);
                uint32_t addr = qs + swz(row, kc * 2 + (lane >> 4));
                LDMX4(qf[rt][kc][0], qf[rt][kc][1], qf[rt][kc][2], qf[rt][kc][3], addr);
            }
    }
    __syncthreads();

    // hoisted per-thread fragment offsets (relative to stage base)
    uint32_t koff[4][4], voff[4][4];
    #pragma unroll
    for (int kc = 0; kc < 4; kc++) {
        #pragma unroll
        for (int nt2 = 0; nt2 < 4; nt2++)
            koff[kc][nt2] = swz(nt2 * 16 + (lane & 15), kc * 2 + (lane >> 4));
        #pragma unroll
        for (int g2 = 0; g2 < 4; g2++)
            voff[kc][g2] = swz(kc * 16 + (lane & 15), g2 * 2 + (lane >> 4));
    }

    float o[2][8][4];
    #pragma unroll
    for (int rt = 0; rt < 2; rt++)
        #pragma unroll
        for (int nt = 0; nt < 8; nt++)
            #pragma unroll
            for (int r = 0; r < 4; r++) o[rt][nt][r] = 0.0f;
    float m_lo[2] = {-3.0e38f, -3.0e38f}, m_hi[2] = {-3.0e38f, -3.0e38f};
    float l_lo[2] = {0.0f, 0.0f},         l_hi[2] = {0.0f, 0.0f};

    auto kvload = [&](int stg, int c0) {
        uint32_t ks = smem_u32(sm.s.k[stg]);
        uint32_t vs = smem_u32(sm.s.v[stg]);
        #pragma unroll
        for (int i = 0; i < 4; i++) {
            int linear = i * 128 + tid;
            int r = linear >> 3, c16 = linear & 7;
            CP_ASYNC16(ks + swz(r, c16), K + baseIn + (long)(c0 + r) * lda + c16 * 8);
        }
        #pragma unroll
        for (int i = 0; i < 4; i++) {
            int linear = i * 128 + tid;
            int r = linear >> 3, c16 = linear & 7;
            CP_ASYNC16(vs + swz(r, c16), V + baseIn + (long)(c0 + r) * lda + c16 * 8);
        }
    };

    const int NT = SQ / 64;
    kvload(0, 0);  CP_COMMIT;
    kvload(1, 64); CP_COMMIT;

    for (int t = 0; t < NT; t++) {
        if (t < NT - 1) { CP_WAIT1; } else { CP_WAIT0; }
        __syncthreads();
        if (t + 2 < NT) { kvload((t + 2) % 3, (t + 2) * 64); CP_COMMIT; }

        const uint32_t ks = smem_u32(sm.s.k[t % 3]);
        const uint32_t vs = smem_u32(sm.s.v[t % 3]);

        // ---- S = Q @ K^T
        float s[2][8][4];
        #pragma unroll
        for (int rt = 0; rt < 2; rt++)
            #pragma unroll
            for (int nt = 0; nt < 8; nt++)
                #pragma unroll
                for (int r = 0; r < 4; r++) s[rt][nt][r] = 0.0f;

        #pragma unroll
        for (int kc = 0; kc < 4; kc++) {
            uint32_t br[4][4];
            #pragma unroll
            for (int nt2 = 0; nt2 < 4; nt2++)
                LDMX4(br[nt2][0], br[nt2][1], br[nt2][2], br[nt2][3],
                      ks + koff[kc][nt2]);
            #pragma unroll
            for (int rt = 0; rt < 2; rt++)
                #pragma unroll
                for (int nt = 0; nt < 8; nt++)
                    MMA16816(s[rt][nt], qf[rt][kc],
                             br[nt >> 1][nt & 1], br[nt >> 1][(nt & 1) + 2]);
        }

        // ---- online softmax (logit = s * 0.125)
        uint32_t pp[2][8][2];
        #pragma unroll
        for (int rt = 0; rt < 2; rt++) {
            float mt_lo = -3.0e38f, mt_hi = -3.0e38f;
            #pragma unroll
            for (int nt = 0; nt < 8; nt++) {
                mt_lo = fmaxf(mt_lo, fmaxf(s[rt][nt][0], s[rt][nt][1]));
                mt_hi = fmaxf(mt_hi, fmaxf(s[rt][nt][2], s[rt][nt][3]));
            }
            mt_lo *= 0.125f; mt_hi *= 0.125f;
            mt_lo = fmaxf(mt_lo, __shfl_xor_sync(0xffffffffu, mt_lo, 1));
            mt_lo = fmaxf(mt_lo, __shfl_xor_sync(0xffffffffu, mt_lo, 2));
            mt_hi = fmaxf(mt_hi, __shfl_xor_sync(0xffffffffu, mt_hi, 1));
            mt_hi = fmaxf(mt_hi, __shfl_xor_sync(0xffffffffu, mt_hi, 2));

            const float mn_lo = fmaxf(m_lo[rt], mt_lo);
            const float mn_hi = fmaxf(m_hi[rt], mt_hi);
            const float corr_lo = __expf(m_lo[rt] - mn_lo);
            const float corr_hi = __expf(m_hi[rt] - mn_hi);
            m_lo[rt] = mn_lo; m_hi[rt] = mn_hi;

            float rs_lo = 0.0f, rs_hi = 0.0f;
            #pragma unroll
            for (int nt = 0; nt < 8; nt++) {
                float p0 = __expf(fmaf(s[rt][nt][0], 0.125f, -mn_lo));
                float p1 = __expf(fmaf(s[rt][nt][1], 0.125f, -mn_lo));
                float p2 = __expf(fmaf(s[rt][nt][2], 0.125f, -mn_hi));
                float p3 = __expf(fmaf(s[rt][nt][3], 0.125f, -mn_hi));
                rs_lo += p0 + p1; rs_hi += p2 + p3;
                __half2 h01 = __floats2half2_rn(p0, p1);
                __half2 h23 = __floats2half2_rn(p2, p3);
                pp[rt][nt][0] = *(uint32_t*)&h01;
                pp[rt][nt][1] = *(uint32_t*)&h23;
            }
            rs_lo += __shfl_xor_sync(0xffffffffu, rs_lo, 1);
            rs_lo += __shfl_xor_sync(0xffffffffu, rs_lo, 2);
            rs_hi += __shfl_xor_sync(0xffffffffu, rs_hi, 1);
            rs_hi += __shfl_xor_sync(0xffffffffu, rs_hi, 2);
            l_lo[rt] = l_lo[rt] * corr_lo + rs_lo;
            l_hi[rt] = l_hi[rt] * corr_hi + rs_hi;
            #pragma unroll
            for (int nt = 0; nt < 8; nt++) {
                o[rt][nt][0] *= corr_lo; o[rt][nt][1] *= corr_lo;
                o[rt][nt][2] *= corr_hi; o[rt][nt][3] *= corr_hi;
            }
        }

        // ---- O += P @ V via ldmatrix.trans on natural [key][dh] tiles
        #pragma unroll
        for (int kc = 0; kc < 4; kc++) {
            uint32_t vr[4][4];
            #pragma unroll
            for (int g2 = 0; g2 < 4; g2++)
                LDMX4T(vr[g2][0], vr[g2][1], vr[g2][2], vr[g2][3],
                       vs + voff[kc][g2]);
            #pragma unroll
            for (int rt = 0; rt < 2; rt++) {
                uint32_t a[4] = { pp[rt][2 * kc][0], pp[rt][2 * kc][1],
                                  pp[rt][2 * kc + 1][0], pp[rt][2 * kc + 1][1] };
                #pragma unroll
                for (int nt = 0; nt < 8; nt++)
                    MMA16816(o[rt][nt], a,
                             vr[nt >> 1][(nt & 1) * 2], vr[nt >> 1][(nt & 1) * 2 + 1]);
            }
        }
    }

    #pragma unroll
    for (int rt = 0; rt < 2; rt++) {
        const float inv_lo = 1.0f / l_lo[rt], inv_hi = 1.0f / l_hi[rt];
        const long row_lo = q0 + warp * 32 + rt * 16 + (lane >> 2);
        #pragma unroll
        for (int nt = 0; nt < 8; nt++) {
            int col = nt * 8 + 2 * (lane & 3);
            *(__half2*)&O[baseOut + row_lo * DM + col] =
                __floats2half2_rn(o[rt][nt][0] * inv_lo, o[rt][nt][1] * inv_lo);
            *(__half2*)&O[baseOut + (row_lo + 8) * DM + col] =
                __floats2half2_rn(o[rt][nt][2] * inv_hi, o[rt][nt][3] * inv_hi);
        }
    }
}

// ---------------------------------------------------------------------------
// LayerNorm over rows of length 1024; optional secondary fp16 output.
// ---------------------------------------------------------------------------
template<bool DUAL>
__global__ void __launch_bounds__(256)
layernorm1024(const float* __restrict__ x, const float* __restrict__ g,
              const float* __restrict__ b, float* __restrict__ out,
              __half* __restrict__ out16)
{
    const long row = blockIdx.x;
    const float* p = x + row * (long)DM;
    float v[4];
    float s = 0.0f;
    #pragma unroll
    for (int i = 0; i < 4; i++) {
        v[i] = p[threadIdx.x + i * 256];
        s += v[i];
    }
    s = block_reduce_sum(s);
    const float mean = s * (1.0f / DM);
    float s2 = 0.0f;
    #pragma unroll
    for (int i = 0; i < 4; i++) {
        float d = v[i] - mean;
        s2 += d * d;
    }
    s2 = block_reduce_sum(s2);
    const float rstd = rsqrtf(s2 * (1.0f / DM) + 1e-5f);
    #pragma unroll
    for (int i = 0; i < 4; i++) {
        int c = threadIdx.x + i * 256;
        float y = (v[i] - mean) * rstd * g[c] + b[c];
        out[row * (long)DM + c] = y;
        if (DUAL) out16[row * (long)DM + c] = __float2half(y);
    }
}

// ---------------------------------------------------------------------------
// Launch orchestration (graph-capturable: kernel launches only)
// ---------------------------------------------------------------------------
extern "C" void kernel_launch(void* const* d_in, const int* in_sizes, int n_in,
                              void* d_out, int out_size)
{
    const float* src   = (const float*)d_in[0];
    const float* qw    = (const float*)d_in[1];
    const float* qb    = (const float*)d_in[2];
    const float* kw    = (const float*)d_in[3];
    const float* kb    = (const float*)d_in[4];
    const float* vw    = (const float*)d_in[5];
    const float* vb    = (const float*)d_in[6];
    const float* ow    = (const float*)d_in[7];
    const float* ob    = (const float*)d_in[8];
    const float* w1    = (const float*)d_in[9];
    const float* b1    = (const float*)d_in[10];
    const float* w2    = (const float*)d_in[11];
    const float* b2    = (const float*)d_in[12];
    const float* g1    = (const float*)d_in[13];
    const float* beta1 = (const float*)d_in[14];
    const float* g2    = (const float*)d_in[15];
    const float* beta2 = (const float*)d_in[16];
    float* out = (float*)d_out;

    __half *srch, *wqkvh, *owh, *w1h, *w2h, *qkvh, *ctxh, *x1h, *ffh;
    float  *bqkv, *t0, *t1, *t2;
    cudaGetSymbolAddress((void**)&srch,  g_srch);
    cudaGetSymbolAddress((void**)&wqkvh, g_wqkvh);
    cudaGetSymbolAddress((void**)&bqkv,  g_bqkv);
    cudaGetSymbolAddress((void**)&owh,   g_owh);
    cudaGetSymbolAddress((void**)&w1h,   g_w1h);
    cudaGetSymbolAddress((void**)&w2h,   g_w2h);
    cudaGetSymbolAddress((void**)&qkvh,  g_qkvh);
    cudaGetSymbolAddress((void**)&ctxh,  g_ctxh);
    cudaGetSymbolAddress((void**)&x1h,   g_x1h);
    cudaGetSymbolAddress((void**)&ffh,   g_ffh);
    cudaGetSymbolAddress((void**)&t0,    g_t0);
    cudaGetSymbolAddress((void**)&t1,    g_t1);
    cudaGetSymbolAddress((void**)&t2,    g_t2);

    // 96 KB dynamic smem (3 stages x 32 KB); host-side, capture-safe
    const int SMEM = 96 * 1024;
    cudaFuncSetAttribute(gemm16<false,false,__half>,
                         cudaFuncAttributeMaxDynamicSharedMemorySize, SMEM);
    cudaFuncSetAttribute(gemm16<false,true,float>,
                         cudaFuncAttributeMaxDynamicSharedMemorySize, SMEM);
    cudaFuncSetAttribute(gemm16<true,false,__half>,
                         cudaFuncAttributeMaxDynamicSharedMemorySize, SMEM);

    const dim3 blk(256);

    // ---- one-shot conversions
    convert_all<<<16384, blk>>>(src, qw, kw, vw, ow, w1, w2,
                                srch, wqkvh, owh, w1h, w2h);
    pack_bias<<<12, blk>>>(qb, kb, vb, bqkv);

    // ---- fused QKV projection: qkv[4096, 3072] = srch @ wqkv^T + bqkv
    {
        dim3 g(3 * DM / 128, MROWS / 128);
        gemm16<false,false,__half><<<g, blk, SMEM>>>(
            srch, DM, wqkvh, DM, bqkv, nullptr, qkvh, 3 * DM, MROWS, 3 * DM, DM);
    }

    // ---- fused attention on packed QKV (lda = 3*DM); ctxh fp16 out
    {
        dim3 g(SQ / 128, BZ * NH);
        flash_hmma<<<g, dim3(128)>>>(qkvh, qkvh + DM, qkvh + 2 * DM, 3 * DM, ctxh);
    }

    // ---- O projection + residual: y(t1) = ctxh @ ow^T + ob + src
    {
        dim3 g(DM / 128, MROWS / 128);
        gemm16<false,true,float><<<g, blk, SMEM>>>(
            ctxh, DM, owh, DM, ob, src, t1, DM, MROWS, DM, DM);
    }

    // ---- LN1: x1 = LN(y) -> f32 (t2) + fp16 (x1h)
    layernorm1024<true><<<MROWS, blk>>>(t1, g1, beta1, t2, x1h);

    // ---- FF1: ffh = relu(x1h @ w1h^T + b1) (fp16 out)
    {
        dim3 g(FFD / 128, MROWS / 128);
        gemm16<true,false,__half><<<g, blk, SMEM>>>(
            x1h, DM, w1h, DM, b1, nullptr, ffh, FFD, MROWS, FFD, DM);
    }

    // ---- FF2 + residual: y2(t0) = ffh @ w2h^T + b2 + x1(t2)
    {
        dim3 g(DM / 128, MROWS / 128);
        gemm16<false,true,float><<<g, blk, SMEM>>>(
            ffh, FFD, w2h, FFD, b2, t2, t0, DM, MROWS, DM, FFD);
    }

    // ---- LN2 -> output
    layernorm1024<false><<<MROWS, blk>>>(t0, g2, beta2, out, nullptr);
}